// round 10
// baseline (speedup 1.0000x reference)
#include <cuda_runtime.h>

#define B_ 256
#define T_ 512
#define D_ 128
#define U_ 128
#define C_ 64
#define M_ (B_*T_)

__device__ float g_H[(size_t)M_ * U_];

typedef unsigned long long ull;

__device__ __forceinline__ ull pk2(float x, float y) {
    ull r; asm("mov.b64 %0, {%1,%2};" : "=l"(r) : "f"(x), "f"(y)); return r;
}
__device__ __forceinline__ void upk2(ull v, float& x, float& y) {
    asm("mov.b64 {%0,%1}, %2;" : "=f"(x), "=f"(y) : "l"(v));
}
__device__ __forceinline__ ull ffma2(ull a, ull b, ull c) {
    ull d; asm("fma.rn.f32x2 %0, %1, %2, %3;" : "=l"(d) : "l"(a), "l"(b), "l"(c)); return d;
}
__device__ __forceinline__ float tanh_fast(float x) {
    float y; asm("tanh.approx.f32 %0, %1;" : "=f"(y) : "f"(x)); return y;
}

// ---------------------------------------------------------------------------
// K1: H = tanh(X @ W1 + b1). Unchanged (108us).
// ---------------------------------------------------------------------------
__global__ void __launch_bounds__(256, 2)
k1_in_gemm(const float* __restrict__ X, const float* __restrict__ W1,
           const float* __restrict__ b1)
{
    extern __shared__ float smem[];
    float2* Wp = (float2*)smem;
    float*  Xs = smem + 16384;
    const int tid = threadIdx.x;
    const int m0 = blockIdx.x * 64;

    {
        const int c4 = (tid & 31) * 4;
        const int kp0 = tid >> 5;
        #pragma unroll
        for (int pass = 0; pass < 8; pass++) {
            int kp = kp0 + pass * 8;
            float4 a = *(const float4*)(W1 + (size_t)(2*kp)   * 128 + c4);
            float4 b = *(const float4*)(W1 + (size_t)(2*kp+1) * 128 + c4);
            float2* w = Wp + kp*128 + c4;
            w[0] = make_float2(a.x, b.x);
            w[1] = make_float2(a.y, b.y);
            w[2] = make_float2(a.z, b.z);
            w[3] = make_float2(a.w, b.w);
        }
    }
    {
        const int q  = (tid & 31) * 4;
        const int r0 = tid >> 5;
        #pragma unroll
        for (int pass = 0; pass < 8; pass++) {
            int row = r0 + pass * 8;
            *(float4*)(Xs + row*128 + q) =
                *(const float4*)(X + (size_t)(m0+row)*128 + q);
        }
    }
    __syncthreads();

    const int tc = tid & 31;
    const int tr = tid >> 5;
    ull acc[8][4];
    #pragma unroll
    for (int i = 0; i < 8; i++)
        #pragma unroll
        for (int c = 0; c < 4; c++) acc[i][c] = 0ULL;

    const float*  xbase = Xs + tr * 8 * 128;
    const float2* wbase = Wp + tc * 4;

    #pragma unroll 8
    for (int kp = 0; kp < 64; kp++) {
        ulonglong2 wv0 = *(const ulonglong2*)(wbase + (size_t)kp*128);
        ulonglong2 wv1 = *(const ulonglong2*)(wbase + (size_t)kp*128 + 2);
        #pragma unroll
        for (int i = 0; i < 8; i++) {
            ull xp = *(const ull*)(xbase + i*128 + 2*kp);
            acc[i][0] = ffma2(xp, wv0.x, acc[i][0]);
            acc[i][1] = ffma2(xp, wv0.y, acc[i][1]);
            acc[i][2] = ffma2(xp, wv1.x, acc[i][2]);
            acc[i][3] = ffma2(xp, wv1.y, acc[i][3]);
        }
    }

    float bb[4];
    #pragma unroll
    for (int c = 0; c < 4; c++) bb[c] = __ldg(b1 + tc*4 + c);

    #pragma unroll
    for (int i = 0; i < 8; i++) {
        int row = m0 + tr*8 + i;
        float4 o; float x, y;
        upk2(acc[i][0], x, y); o.x = tanh_fast(x + y + bb[0]);
        upk2(acc[i][1], x, y); o.y = tanh_fast(x + y + bb[1]);
        upk2(acc[i][2], x, y); o.z = tanh_fast(x + y + bb[2]);
        upk2(acc[i][3], x, y); o.w = tanh_fast(x + y + bb[3]);
        *(float4*)(g_H + (size_t)row*128 + tc*4) = o;
    }
}

// ---------------------------------------------------------------------------
// K2 v4: k-split recurrence (4x less smem writeback) + warp-specialized head.
// 128 CTAs x 384 thr. Rec threads 0..255: 2 chains; thread j (j=tid&127):
// k-slice s=j&3 (32 floats, 8 LDS.128), cols 4(j>>2)..+3 (W2 = 64 f32x2 regs).
// Partials all-reduced over 4-lane groups (shfl.xor 1,2), lane keeps col j.
// y-ring rows k-swizzled: slice stride 36 floats (conflict-free, 16B-aligned).
// Head threads 256..383: previous 16-step block's y @ Wc + bc -> out.
// ---------------------------------------------------------------------------
#define ST_ROW 144   // 4 slices x 36 floats = 576B = 36x16

__global__ void __launch_bounds__(384, 1)
k2_fused(const float* __restrict__ W2, const float* __restrict__ b2,
         const float* __restrict__ Wc, const float* __restrict__ bc,
         float* __restrict__ out)
{
    extern __shared__ float sm[];
    float2* WcP  = (float2*)sm;           // [64 kp][64 c] float2 = 32KB
    float*  hist = sm + 8192;             // [2][32][ST_ROW] = 36.9KB

    const int tid = threadIdx.x;

    for (int idx = tid; idx < 64 * 64; idx += 384) {
        int kp = idx >> 6, c = idx & 63;
        WcP[kp * 64 + c] = make_float2(__ldg(Wc + (size_t)(2*kp)   * 64 + c),
                                       __ldg(Wc + (size_t)(2*kp+1) * 64 + c));
    }

    if (tid < 256) {
        // ================= RECURRENCE ROLE =================
        const int chain = tid >> 7;
        const int j     = tid & 127;
        const int b     = blockIdx.x * 2 + chain;
        const int s4    = j & 3;           // k-slice
        const int cbase = j & ~3;          // column group base (= 4*(j>>2))

        // W2: 4 columns x 16 k-pairs of my slice
        ull w0[16], w1[16], w2[16], w3[16];
        #pragma unroll
        for (int p = 0; p < 16; p++) {
            int k = 32 * s4 + 2 * p;
            const float* ra = W2 + (size_t)k * 128 + cbase;
            const float* rb = W2 + (size_t)(k + 1) * 128 + cbase;
            w0[p] = pk2(__ldg(ra + 0), __ldg(rb + 0));
            w1[p] = pk2(__ldg(ra + 1), __ldg(rb + 1));
            w2[p] = pk2(__ldg(ra + 2), __ldg(rb + 2));
            w3[p] = pk2(__ldg(ra + 3), __ldg(rb + 3));
        }
        const float b2v = __ldg(b2 + j);

        float* myhist = hist + chain * (32 * ST_ROW);
        const int widx = 36 * (j >> 5) + (j & 31);   // y[k=j] swizzled slot
        const int roff = 36 * s4;                    // my read slice offset

        myhist[31 * ST_ROW + widx] = 0.0f;           // y_{-1} = 0
        __syncthreads();                             // pairs with head sync

        const float* Hp = g_H + (size_t)b * (T_*128) + j;
        float hr0 = Hp[0];
        float hr1 = Hp[128];

        #pragma unroll 1
        for (int blk = 0; blk < 33; blk++) {
            if (blk < 32) {
                const int t0 = blk * 16;
                #pragma unroll 4
                for (int u = 0; u < 16; u++) {
                    float hv = (u & 1) ? hr1 : hr0;
                    int tp = t0 + u + 2;
                    float hn = 0.0f;
                    if (tp < T_) hn = Hp[(size_t)tp * 128];
                    if (u & 1) hr1 = hn; else hr0 = hn;

                    const ulonglong2* sp = (const ulonglong2*)
                        (myhist + (((t0 + u + 31) & 31) * ST_ROW) + roff);

                    ull a0 = 0ULL, a1 = 0ULL, a2 = 0ULL, a3 = 0ULL;
                    #define MAC4(yp, p) \
                        a0 = ffma2(yp, w0[p], a0); a1 = ffma2(yp, w1[p], a1); \
                        a2 = ffma2(yp, w2[p], a2); a3 = ffma2(yp, w3[p], a3);
                    {
                        ulonglong2 va = sp[0], vb = sp[1], vc = sp[2], vd = sp[3];
                        MAC4(va.x, 0)  MAC4(va.y, 1)  MAC4(vb.x, 2)  MAC4(vb.y, 3)
                        MAC4(vc.x, 4)  MAC4(vc.y, 5)  MAC4(vd.x, 6)  MAC4(vd.y, 7)
                        va = sp[4]; vb = sp[5]; vc = sp[6]; vd = sp[7];
                        MAC4(va.x, 8)  MAC4(va.y, 9)  MAC4(vb.x,10)  MAC4(vb.y,11)
                        MAC4(vc.x,12)  MAC4(vc.y,13)  MAC4(vd.x,14)  MAC4(vd.y,15)
                    }
                    #undef MAC4

                    float xa, ya, r0, r1, r2, r3;
                    upk2(a0, xa, ya); r0 = xa + ya;
                    upk2(a1, xa, ya); r1 = xa + ya;
                    upk2(a2, xa, ya); r2 = xa + ya;
                    upk2(a3, xa, ya); r3 = xa + ya;
                    r0 += __shfl_xor_sync(0xffffffffu, r0, 1);
                    r1 += __shfl_xor_sync(0xffffffffu, r1, 1);
                    r2 += __shfl_xor_sync(0xffffffffu, r2, 1);
                    r3 += __shfl_xor_sync(0xffffffffu, r3, 1);
                    r0 += __shfl_xor_sync(0xffffffffu, r0, 2);
                    r1 += __shfl_xor_sync(0xffffffffu, r1, 2);
                    r2 += __shfl_xor_sync(0xffffffffu, r2, 2);
                    r3 += __shfl_xor_sync(0xffffffffu, r3, 2);
                    float rlo = (j & 1) ? r1 : r0;
                    float rhi = (j & 1) ? r3 : r2;
                    float rr  = (j & 2) ? rhi : rlo;

                    float yv = hv + tanh_fast(rr + b2v);
                    myhist[((t0 + u) & 31) * ST_ROW + widx] = yv;
                    asm volatile("bar.sync %0, 128;" :: "r"(chain + 1) : "memory");
                }
            }
            __syncthreads();   // block boundary (all 384)
        }
    } else {
        // ================= HEAD ROLE =================
        const int htid    = tid - 256;
        const int chain_h = htid >> 6;
        const int q       = htid & 63;
        const int r0      = (q >> 4) * 4;
        const int c4      = (q & 15) * 4;
        const int b       = blockIdx.x * 2 + chain_h;

        float bb[4];
        #pragma unroll
        for (int c = 0; c < 4; c++) bb[c] = __ldg(bc + c4 + c);

        const float* myhist = hist + chain_h * (32 * ST_ROW);

        __syncthreads();   // pairs with rec init sync

        #pragma unroll 1
        for (int blk = 0; blk < 33; blk++) {
            if (blk > 0) {
                const int t0h = (blk - 1) * 16;
                const float* yr[4];
                #pragma unroll
                for (int r = 0; r < 4; r++)
                    yr[r] = myhist + (((t0h + r0 + r) & 31) * ST_ROW);

                ull acc[4][4];
                #pragma unroll
                for (int r = 0; r < 4; r++)
                    #pragma unroll
                    for (int c = 0; c < 4; c++) acc[r][c] = 0ULL;

                #pragma unroll 4
                for (int kp = 0; kp < 64; kp++) {
                    const int off = 36 * (kp >> 4) + 2 * (kp & 15);  // swizzled pair
                    ulonglong2 wc0 = *(const ulonglong2*)(WcP + kp*64 + c4);
                    ulonglong2 wc1 = *(const ulonglong2*)(WcP + kp*64 + c4 + 2);
                    #pragma unroll
                    for (int r = 0; r < 4; r++) {
                        ull yv = *(const ull*)(yr[r] + off);
                        acc[r][0] = ffma2(yv, wc0.x, acc[r][0]);
                        acc[r][1] = ffma2(yv, wc0.y, acc[r][1]);
                        acc[r][2] = ffma2(yv, wc1.x, acc[r][2]);
                        acc[r][3] = ffma2(yv, wc1.y, acc[r][3]);
                    }
                }

                #pragma unroll
                for (int r = 0; r < 4; r++) {
                    float4 o; float x, y;
                    upk2(acc[r][0], x, y); o.x = x + y + bb[0];
                    upk2(acc[r][1], x, y); o.y = x + y + bb[1];
                    upk2(acc[r][2], x, y); o.z = x + y + bb[2];
                    upk2(acc[r][3], x, y); o.w = x + y + bb[3];
                    *(float4*)(out + ((size_t)b * T_ + t0h + r0 + r) * 64 + c4) = o;
                }
            }
            __syncthreads();   // block boundary (all 384)
        }
    }
}

extern "C" void kernel_launch(void* const* d_in, const int* in_sizes, int n_in,
                              void* d_out, int out_size) {
    (void)in_sizes; (void)n_in; (void)out_size;
    const float* X  = (const float*)d_in[0];
    const float* W1 = (const float*)d_in[1];
    const float* b1 = (const float*)d_in[2];
    const float* W2 = (const float*)d_in[3];
    const float* b2 = (const float*)d_in[4];
    const float* Wc = (const float*)d_in[5];
    const float* bc = (const float*)d_in[6];
    float* out = (float*)d_out;

    cudaFuncSetAttribute(k1_in_gemm, cudaFuncAttributeMaxDynamicSharedMemorySize, 98304);
    cudaFuncSetAttribute(k2_fused,   cudaFuncAttributeMaxDynamicSharedMemorySize, 98304);

    k1_in_gemm<<<M_/64, 256, 98304>>>(X, W1, b1);

    const int k2_smem = (8192 + 2*32*ST_ROW) * 4;
    k2_fused<<<B_/2, 384, k2_smem>>>(W2, b2, Wc, bc, out);
}

// round 11
// speedup vs baseline: 1.0467x; 1.0467x over previous
#include <cuda_runtime.h>

#define B_ 256
#define T_ 512
#define D_ 128
#define U_ 128
#define C_ 64
#define M_ (B_*T_)

// padded by 16 rows so the H-prefetch can run unconditionally past t=T-1
__device__ float g_H[(size_t)(M_ + 16) * U_];

typedef unsigned long long ull;

__device__ __forceinline__ ull pk2(float x, float y) {
    ull r; asm("mov.b64 %0, {%1,%2};" : "=l"(r) : "f"(x), "f"(y)); return r;
}
__device__ __forceinline__ void upk2(ull v, float& x, float& y) {
    asm("mov.b64 {%0,%1}, %2;" : "=f"(x), "=f"(y) : "l"(v));
}
__device__ __forceinline__ ull ffma2(ull a, ull b, ull c) {
    ull d; asm("fma.rn.f32x2 %0, %1, %2, %3;" : "=l"(d) : "l"(a), "l"(b), "l"(c)); return d;
}
__device__ __forceinline__ float tanh_fast(float x) {
    float y; asm("tanh.approx.f32 %0, %1;" : "=f"(y) : "f"(x)); return y;
}

// ---------------------------------------------------------------------------
// K1: H = tanh(X @ W1 + b1). Unchanged (108us).
// ---------------------------------------------------------------------------
__global__ void __launch_bounds__(256, 2)
k1_in_gemm(const float* __restrict__ X, const float* __restrict__ W1,
           const float* __restrict__ b1)
{
    extern __shared__ float smem[];
    float2* Wp = (float2*)smem;
    float*  Xs = smem + 16384;
    const int tid = threadIdx.x;
    const int m0 = blockIdx.x * 64;

    {
        const int c4 = (tid & 31) * 4;
        const int kp0 = tid >> 5;
        #pragma unroll
        for (int pass = 0; pass < 8; pass++) {
            int kp = kp0 + pass * 8;
            float4 a = *(const float4*)(W1 + (size_t)(2*kp)   * 128 + c4);
            float4 b = *(const float4*)(W1 + (size_t)(2*kp+1) * 128 + c4);
            float2* w = Wp + kp*128 + c4;
            w[0] = make_float2(a.x, b.x);
            w[1] = make_float2(a.y, b.y);
            w[2] = make_float2(a.z, b.z);
            w[3] = make_float2(a.w, b.w);
        }
    }
    {
        const int q  = (tid & 31) * 4;
        const int r0 = tid >> 5;
        #pragma unroll
        for (int pass = 0; pass < 8; pass++) {
            int row = r0 + pass * 8;
            *(float4*)(Xs + row*128 + q) =
                *(const float4*)(X + (size_t)(m0+row)*128 + q);
        }
    }
    __syncthreads();

    const int tc = tid & 31;
    const int tr = tid >> 5;
    ull acc[8][4];
    #pragma unroll
    for (int i = 0; i < 8; i++)
        #pragma unroll
        for (int c = 0; c < 4; c++) acc[i][c] = 0ULL;

    const float*  xbase = Xs + tr * 8 * 128;
    const float2* wbase = Wp + tc * 4;

    #pragma unroll 8
    for (int kp = 0; kp < 64; kp++) {
        ulonglong2 wv0 = *(const ulonglong2*)(wbase + (size_t)kp*128);
        ulonglong2 wv1 = *(const ulonglong2*)(wbase + (size_t)kp*128 + 2);
        #pragma unroll
        for (int i = 0; i < 8; i++) {
            ull xp = *(const ull*)(xbase + i*128 + 2*kp);
            acc[i][0] = ffma2(xp, wv0.x, acc[i][0]);
            acc[i][1] = ffma2(xp, wv0.y, acc[i][1]);
            acc[i][2] = ffma2(xp, wv1.x, acc[i][2]);
            acc[i][3] = ffma2(xp, wv1.y, acc[i][3]);
        }
    }

    float bb[4];
    #pragma unroll
    for (int c = 0; c < 4; c++) bb[c] = __ldg(b1 + tc*4 + c);

    #pragma unroll
    for (int i = 0; i < 8; i++) {
        int row = m0 + tr*8 + i;
        float4 o; float x, y;
        upk2(acc[i][0], x, y); o.x = tanh_fast(x + y + bb[0]);
        upk2(acc[i][1], x, y); o.y = tanh_fast(x + y + bb[1]);
        upk2(acc[i][2], x, y); o.z = tanh_fast(x + y + bb[2]);
        upk2(acc[i][3], x, y); o.w = tanh_fast(x + y + bb[3]);
        *(float4*)(g_H + (size_t)row*128 + tc*4) = o;
    }
}

// ---------------------------------------------------------------------------
// K2 v5: R9 structure, de-bloated loop.
//  - branchless H prefetch (g_H padded): no BSSY/BSYNC in the hot loop
//  - u-loop unroll 4 (body ~6KB, fits I$ L0) instead of full 16
//  - ring addressing via masked index, constants hoisted
// Rec threads 0..255 (2 chains, W2[:,j] in regs, per-step named bars);
// head threads 256..383 compute previous 16-step block's y @ Wc + bc.
// ---------------------------------------------------------------------------
#define ST_ROW 136   // 544B = 34x16; halves at float offsets 0 and 68

__global__ void __launch_bounds__(384, 1)
k2_fused(const float* __restrict__ W2, const float* __restrict__ b2,
         const float* __restrict__ Wc, const float* __restrict__ bc,
         float* __restrict__ out)
{
    extern __shared__ float sm[];
    float2* WcP  = (float2*)sm;           // 32KB
    float*  hist = sm + 8192;             // [2][32][ST_ROW] = 34.8KB

    const int tid = threadIdx.x;

    for (int idx = tid; idx < 64 * 64; idx += 384) {
        int kp = idx >> 6, c = idx & 63;
        WcP[kp * 64 + c] = make_float2(__ldg(Wc + (size_t)(2*kp)   * 64 + c),
                                       __ldg(Wc + (size_t)(2*kp+1) * 64 + c));
    }

    if (tid < 256) {
        // ================= RECURRENCE ROLE =================
        const int chain = tid >> 7;
        const int j     = tid & 127;
        const int b     = blockIdx.x * 2 + chain;

        ull w[64];
        #pragma unroll
        for (int p = 0; p < 64; p++)
            w[p] = pk2(__ldg(W2 + (size_t)(2*p)*128 + j),
                       __ldg(W2 + (size_t)(2*p+1)*128 + j));
        const float b2v = __ldg(b2 + j);

        float* myhist = hist + chain * (32 * ST_ROW);
        const int sidx = (j & 63) + (j >> 6) * 68;

        myhist[31 * ST_ROW + sidx] = 0.0f;    // y_{-1}
        __syncthreads();

        const float* Hp = g_H + (size_t)b * (T_*128) + j;
        float hr[4];
        #pragma unroll
        for (int i = 0; i < 4; i++) hr[i] = Hp[(size_t)i * 128];

        #pragma unroll 1
        for (int blk = 0; blk < 33; blk++) {
            if (blk < 32) {
                const int t0 = blk * 16;
                #pragma unroll 4
                for (int u = 0; u < 16; u++) {
                    const int t = t0 + u;
                    float hv = hr[u & 3];
                    hr[u & 3] = Hp[(size_t)(t + 4) * 128];   // unconditional

                    const float* sb = myhist + (((t + 31) & 31) * ST_ROW);
                    ull a0 = 0ULL, a1 = 0ULL, a2 = 0ULL, a3 = 0ULL;
                    #pragma unroll
                    for (int p = 0; p < 8; p++) {
                        ulonglong2 s0  = *(const ulonglong2*)(sb + 8*p);
                        ulonglong2 s1  = *(const ulonglong2*)(sb + 68 + 8*p);
                        a0 = ffma2(s0.x,  w[4*p+0],  a0);
                        a1 = ffma2(s0.y,  w[4*p+1],  a1);
                        a2 = ffma2(s1.x,  w[32+4*p], a2);
                        a3 = ffma2(s1.y,  w[33+4*p], a3);
                        ulonglong2 s0b = *(const ulonglong2*)(sb + 8*p + 4);
                        ulonglong2 s1b = *(const ulonglong2*)(sb + 68 + 8*p + 4);
                        a0 = ffma2(s0b.x, w[4*p+2],  a0);
                        a1 = ffma2(s0b.y, w[4*p+3],  a1);
                        a2 = ffma2(s1b.x, w[34+4*p], a2);
                        a3 = ffma2(s1b.y, w[35+4*p], a3);
                    }
                    float x0,y0,x1,y1,x2,y2,x3,y3;
                    upk2(a0,x0,y0); upk2(a1,x1,y1);
                    upk2(a2,x2,y2); upk2(a3,x3,y3);
                    float s = ((x0+y0)+(x1+y1)) + ((x2+y2)+(x3+y3)) + b2v;
                    float yv = hv + tanh_fast(s);

                    myhist[(t & 31) * ST_ROW + sidx] = yv;
                    asm volatile("bar.sync %0, 128;" :: "r"(chain + 1) : "memory");
                }
            }
            __syncthreads();
        }
    } else {
        // ================= HEAD ROLE =================
        const int htid    = tid - 256;
        const int chain_h = htid >> 6;
        const int q       = htid & 63;
        const int r0      = (q >> 4) * 4;
        const int c4      = (q & 15) * 4;
        const int b       = blockIdx.x * 2 + chain_h;

        float bb[4];
        #pragma unroll
        for (int c = 0; c < 4; c++) bb[c] = __ldg(bc + c4 + c);

        const float* myhist = hist + chain_h * (32 * ST_ROW);

        __syncthreads();

        #pragma unroll 1
        for (int blk = 0; blk < 33; blk++) {
            if (blk > 0) {
                const int t0h = (blk - 1) * 16;
                const float* yr[4];
                #pragma unroll
                for (int r = 0; r < 4; r++)
                    yr[r] = myhist + (((t0h + r0 + r) & 31) * ST_ROW);

                ull acc[4][4];
                #pragma unroll
                for (int r = 0; r < 4; r++)
                    #pragma unroll
                    for (int c = 0; c < 4; c++) acc[r][c] = 0ULL;

                #pragma unroll 4
                for (int kp = 0; kp < 64; kp++) {
                    const int off = (kp < 32) ? (2*kp) : (68 + 2*(kp-32));
                    ulonglong2 wc0 = *(const ulonglong2*)(WcP + kp*64 + c4);
                    ulonglong2 wc1 = *(const ulonglong2*)(WcP + kp*64 + c4 + 2);
                    #pragma unroll
                    for (int r = 0; r < 4; r++) {
                        ull yv = *(const ull*)(yr[r] + off);
                        acc[r][0] = ffma2(yv, wc0.x, acc[r][0]);
                        acc[r][1] = ffma2(yv, wc0.y, acc[r][1]);
                        acc[r][2] = ffma2(yv, wc1.x, acc[r][2]);
                        acc[r][3] = ffma2(yv, wc1.y, acc[r][3]);
                    }
                }

                #pragma unroll
                for (int r = 0; r < 4; r++) {
                    float4 o; float x, y;
                    upk2(acc[r][0], x, y); o.x = x + y + bb[0];
                    upk2(acc[r][1], x, y); o.y = x + y + bb[1];
                    upk2(acc[r][2], x, y); o.z = x + y + bb[2];
                    upk2(acc[r][3], x, y); o.w = x + y + bb[3];
                    *(float4*)(out + ((size_t)b * T_ + t0h + r0 + r) * 64 + c4) = o;
                }
            }
            __syncthreads();
        }
    }
}

extern "C" void kernel_launch(void* const* d_in, const int* in_sizes, int n_in,
                              void* d_out, int out_size) {
    (void)in_sizes; (void)n_in; (void)out_size;
    const float* X  = (const float*)d_in[0];
    const float* W1 = (const float*)d_in[1];
    const float* b1 = (const float*)d_in[2];
    const float* W2 = (const float*)d_in[3];
    const float* b2 = (const float*)d_in[4];
    const float* Wc = (const float*)d_in[5];
    const float* bc = (const float*)d_in[6];
    float* out = (float*)d_out;

    cudaFuncSetAttribute(k1_in_gemm, cudaFuncAttributeMaxDynamicSharedMemorySize, 98304);
    cudaFuncSetAttribute(k2_fused,   cudaFuncAttributeMaxDynamicSharedMemorySize, 98304);

    k1_in_gemm<<<M_/64, 256, 98304>>>(X, W1, b1);

    const int k2_smem = (8192 + 2*32*ST_ROW) * 4;
    k2_fused<<<B_/2, 384, k2_smem>>>(W2, b2, Wc, bc, out);
}

// round 12
// speedup vs baseline: 1.2224x; 1.1679x over previous
#include <cuda_runtime.h>

#define B_ 256
#define T_ 512
#define D_ 128
#define U_ 128
#define C_ 64
#define M_ (B_*T_)

// padded by 16 rows so head H-preload of the (nonexistent) block 32 is safe
__device__ float g_H[(size_t)(M_ + 16) * U_];

typedef unsigned long long ull;

__device__ __forceinline__ ull pk2(float x, float y) {
    ull r; asm("mov.b64 %0, {%1,%2};" : "=l"(r) : "f"(x), "f"(y)); return r;
}
__device__ __forceinline__ void upk2(ull v, float& x, float& y) {
    asm("mov.b64 {%0,%1}, %2;" : "=f"(x), "=f"(y) : "l"(v));
}
__device__ __forceinline__ ull ffma2(ull a, ull b, ull c) {
    ull d; asm("fma.rn.f32x2 %0, %1, %2, %3;" : "=l"(d) : "l"(a), "l"(b), "l"(c)); return d;
}
__device__ __forceinline__ float tanh_fast(float x) {
    float y; asm("tanh.approx.f32 %0, %1;" : "=f"(y) : "f"(x)); return y;
}

// ---------------------------------------------------------------------------
// K1: H = tanh(X @ W1 + b1). Unchanged (108us).
// ---------------------------------------------------------------------------
__global__ void __launch_bounds__(256, 2)
k1_in_gemm(const float* __restrict__ X, const float* __restrict__ W1,
           const float* __restrict__ b1)
{
    extern __shared__ float smem[];
    float2* Wp = (float2*)smem;
    float*  Xs = smem + 16384;
    const int tid = threadIdx.x;
    const int m0 = blockIdx.x * 64;

    {
        const int c4 = (tid & 31) * 4;
        const int kp0 = tid >> 5;
        #pragma unroll
        for (int pass = 0; pass < 8; pass++) {
            int kp = kp0 + pass * 8;
            float4 a = *(const float4*)(W1 + (size_t)(2*kp)   * 128 + c4);
            float4 b = *(const float4*)(W1 + (size_t)(2*kp+1) * 128 + c4);
            float2* w = Wp + kp*128 + c4;
            w[0] = make_float2(a.x, b.x);
            w[1] = make_float2(a.y, b.y);
            w[2] = make_float2(a.z, b.z);
            w[3] = make_float2(a.w, b.w);
        }
    }
    {
        const int q  = (tid & 31) * 4;
        const int r0 = tid >> 5;
        #pragma unroll
        for (int pass = 0; pass < 8; pass++) {
            int row = r0 + pass * 8;
            *(float4*)(Xs + row*128 + q) =
                *(const float4*)(X + (size_t)(m0+row)*128 + q);
        }
    }
    __syncthreads();

    const int tc = tid & 31;
    const int tr = tid >> 5;
    ull acc[8][4];
    #pragma unroll
    for (int i = 0; i < 8; i++)
        #pragma unroll
        for (int c = 0; c < 4; c++) acc[i][c] = 0ULL;

    const float*  xbase = Xs + tr * 8 * 128;
    const float2* wbase = Wp + tc * 4;

    #pragma unroll 8
    for (int kp = 0; kp < 64; kp++) {
        ulonglong2 wv0 = *(const ulonglong2*)(wbase + (size_t)kp*128);
        ulonglong2 wv1 = *(const ulonglong2*)(wbase + (size_t)kp*128 + 2);
        #pragma unroll
        for (int i = 0; i < 8; i++) {
            ull xp = *(const ull*)(xbase + i*128 + 2*kp);
            acc[i][0] = ffma2(xp, wv0.x, acc[i][0]);
            acc[i][1] = ffma2(xp, wv0.y, acc[i][1]);
            acc[i][2] = ffma2(xp, wv1.x, acc[i][2]);
            acc[i][3] = ffma2(xp, wv1.y, acc[i][3]);
        }
    }

    float bb[4];
    #pragma unroll
    for (int c = 0; c < 4; c++) bb[c] = __ldg(b1 + tc*4 + c);

    #pragma unroll
    for (int i = 0; i < 8; i++) {
        int row = m0 + tr*8 + i;
        float4 o; float x, y;
        upk2(acc[i][0], x, y); o.x = tanh_fast(x + y + bb[0]);
        upk2(acc[i][1], x, y); o.y = tanh_fast(x + y + bb[1]);
        upk2(acc[i][2], x, y); o.z = tanh_fast(x + y + bb[2]);
        upk2(acc[i][3], x, y); o.w = tanh_fast(x + y + bb[3]);
        *(float4*)(g_H + (size_t)row*128 + tc*4) = o;
    }
}

// ---------------------------------------------------------------------------
// K2 v6: ONE CHAIN PER CTA (de-phase-lock). 256 CTAs x 192 thr, 2 CTAs/SM.
// Threads 0..127: recurrence (W2[:,j] in regs, per-step bar.sync 1,128).
// Threads 128..191: head warps — (a) preload next 16-step H-block into smem
// (no LDG in rec loop), (b) out-GEMM of the previous block from the 32-ring.
// Separate CTAs share no barrier -> natural stagger fills latency bubbles.
// ---------------------------------------------------------------------------
#define ST_ROW 136   // 544B = 34x16; halves at float offsets 0 and 68

__global__ void __launch_bounds__(192, 2)
k2_fused(const float* __restrict__ W2, const float* __restrict__ b2,
         const float* __restrict__ Wc, const float* __restrict__ bc,
         float* __restrict__ out)
{
    extern __shared__ float sm[];
    float2* WcP  = (float2*)sm;            // [64 kp][64 c] float2 = 32KB
    float*  hist = sm + 8192;              // [32][ST_ROW] = 17.4KB
    float*  hbuf = sm + 8192 + 32*ST_ROW;  // [2][16*128] = 16KB

    const int tid = threadIdx.x;
    const int b   = blockIdx.x;

    // stage Wc pair-interleaved
    for (int idx = tid; idx < 64 * 64; idx += 192) {
        int kp = idx >> 6, c = idx & 63;
        WcP[kp * 64 + c] = make_float2(__ldg(Wc + (size_t)(2*kp)   * 64 + c),
                                       __ldg(Wc + (size_t)(2*kp+1) * 64 + c));
    }
    // stage H block 0 into hbuf[0]
    {
        const float* Hb = g_H + (size_t)b * (T_*128);
        for (int idx = tid; idx < 512; idx += 192) {       // 512 float4 chunks
            *(float4*)(hbuf + idx*4) = *(const float4*)(Hb + idx*4);
        }
    }

    if (tid < 128) {
        // ================= RECURRENCE ROLE =================
        const int j = tid;

        ull w[64];
        #pragma unroll
        for (int p = 0; p < 64; p++)
            w[p] = pk2(__ldg(W2 + (size_t)(2*p)*128 + j),
                       __ldg(W2 + (size_t)(2*p+1)*128 + j));
        const float b2v = __ldg(b2 + j);

        const int sidx = (j & 63) + (j >> 6) * 68;
        hist[31 * ST_ROW + sidx] = 0.0f;      // y_{-1}
        __syncthreads();

        #pragma unroll 1
        for (int blk = 0; blk < 33; blk++) {
            if (blk < 32) {
                const int t0 = blk * 16;
                const float* hb = hbuf + (blk & 1) * 2048;
                #pragma unroll 4
                for (int u = 0; u < 16; u++) {
                    const int t = t0 + u;
                    float hv = hb[u * 128 + j];            // smem, preloaded

                    const float* sb = hist + (((t + 31) & 31) * ST_ROW);
                    ull a0 = 0ULL, a1 = 0ULL, a2 = 0ULL, a3 = 0ULL;
                    #pragma unroll
                    for (int p = 0; p < 8; p++) {
                        ulonglong2 s0  = *(const ulonglong2*)(sb + 8*p);
                        ulonglong2 s1  = *(const ulonglong2*)(sb + 68 + 8*p);
                        a0 = ffma2(s0.x,  w[4*p+0],  a0);
                        a1 = ffma2(s0.y,  w[4*p+1],  a1);
                        a2 = ffma2(s1.x,  w[32+4*p], a2);
                        a3 = ffma2(s1.y,  w[33+4*p], a3);
                        ulonglong2 s0b = *(const ulonglong2*)(sb + 8*p + 4);
                        ulonglong2 s1b = *(const ulonglong2*)(sb + 68 + 8*p + 4);
                        a0 = ffma2(s0b.x, w[4*p+2],  a0);
                        a1 = ffma2(s0b.y, w[4*p+3],  a1);
                        a2 = ffma2(s1b.x, w[34+4*p], a2);
                        a3 = ffma2(s1b.y, w[35+4*p], a3);
                    }
                    float x0,y0,x1,y1,x2,y2,x3,y3;
                    upk2(a0,x0,y0); upk2(a1,x1,y1);
                    upk2(a2,x2,y2); upk2(a3,x3,y3);
                    float s = ((x0+y0)+(x1+y1)) + ((x2+y2)+(x3+y3)) + b2v;
                    float yv = hv + tanh_fast(s);

                    hist[(t & 31) * ST_ROW + sidx] = yv;
                    asm volatile("bar.sync 1, 128;" ::: "memory");
                }
            }
            __syncthreads();   // block boundary (all 192)
        }
    } else {
        // ================= HEAD ROLE =================
        const int q  = tid - 128;            // 0..63
        const int r0 = (q >> 4) * 4;         // 4 rows of 16
        const int c4 = (q & 15) * 4;         // 4 cols of 64

        float bb[4];
        #pragma unroll
        for (int c = 0; c < 4; c++) bb[c] = __ldg(bc + c4 + c);

        const float* Hb = g_H + (size_t)b * (T_*128);

        __syncthreads();   // pairs with rec init sync

        #pragma unroll 1
        for (int blk = 0; blk < 33; blk++) {
            // (a) preload H block blk+1 into hbuf[(blk+1)&1]
            if (blk < 32) {
                float* dst = hbuf + ((blk + 1) & 1) * 2048;
                const float* src = Hb + (size_t)(blk + 1) * 16 * 128;
                #pragma unroll
                for (int i = 0; i < 8; i++) {
                    int idx = q + 64 * i;                  // 512 chunks / 64 thr
                    *(float4*)(dst + idx*4) = *(const float4*)(src + idx*4);
                }
            }
            // (b) out-GEMM for block blk-1 from the ring
            if (blk > 0) {
                const int t0h = (blk - 1) * 16;
                const float* yr[4];
                #pragma unroll
                for (int r = 0; r < 4; r++)
                    yr[r] = hist + (((t0h + r0 + r) & 31) * ST_ROW);

                ull acc[4][4];
                #pragma unroll
                for (int r = 0; r < 4; r++)
                    #pragma unroll
                    for (int c = 0; c < 4; c++) acc[r][c] = 0ULL;

                #pragma unroll 4
                for (int kp = 0; kp < 64; kp++) {
                    const int off = (kp < 32) ? (2*kp) : (68 + 2*(kp-32));
                    ulonglong2 wc0 = *(const ulonglong2*)(WcP + kp*64 + c4);
                    ulonglong2 wc1 = *(const ulonglong2*)(WcP + kp*64 + c4 + 2);
                    #pragma unroll
                    for (int r = 0; r < 4; r++) {
                        ull yv = *(const ull*)(yr[r] + off);
                        acc[r][0] = ffma2(yv, wc0.x, acc[r][0]);
                        acc[r][1] = ffma2(yv, wc0.y, acc[r][1]);
                        acc[r][2] = ffma2(yv, wc1.x, acc[r][2]);
                        acc[r][3] = ffma2(yv, wc1.y, acc[r][3]);
                    }
                }

                #pragma unroll
                for (int r = 0; r < 4; r++) {
                    float4 o; float x, y;
                    upk2(acc[r][0], x, y); o.x = x + y + bb[0];
                    upk2(acc[r][1], x, y); o.y = x + y + bb[1];
                    upk2(acc[r][2], x, y); o.z = x + y + bb[2];
                    upk2(acc[r][3], x, y); o.w = x + y + bb[3];
                    *(float4*)(out + ((size_t)b * T_ + t0h + r0 + r) * 64 + c4) = o;
                }
            }
            __syncthreads();   // block boundary (all 192)
        }
    }
}

extern "C" void kernel_launch(void* const* d_in, const int* in_sizes, int n_in,
                              void* d_out, int out_size) {
    (void)in_sizes; (void)n_in; (void)out_size;
    const float* X  = (const float*)d_in[0];
    const float* W1 = (const float*)d_in[1];
    const float* b1 = (const float*)d_in[2];
    const float* W2 = (const float*)d_in[3];
    const float* b2 = (const float*)d_in[4];
    const float* Wc = (const float*)d_in[5];
    const float* bc = (const float*)d_in[6];
    float* out = (float*)d_out;

    cudaFuncSetAttribute(k1_in_gemm, cudaFuncAttributeMaxDynamicSharedMemorySize, 98304);
    cudaFuncSetAttribute(k2_fused,   cudaFuncAttributeMaxDynamicSharedMemorySize, 98304);

    k1_in_gemm<<<M_/64, 256, 98304>>>(X, W1, b1);

    const int k2_smem = (8192 + 32*ST_ROW + 2*2048) * 4;   // WcP + ring + hbuf
    k2_fused<<<B_, 192, k2_smem>>>(W2, b2, Wc, bc, out);
}